// round 12
// baseline (speedup 1.0000x reference)
#include <cuda_runtime.h>
#include <cuda_fp16.h>
#include <math.h>
#include <stdint.h>

#define BATCH 4
#define SEQ   2048
#define DMODEL 1024
#define NHEAD 16
#define DHEAD 64
#define MROWS (BATCH * SEQ)   // 8192

// Scratch (device globals: allocation-free, graph-capture safe)
__device__ __half g_xh[MROWS * DMODEL];
__device__ __half g_wq[DMODEL * DMODEL];
__device__ __half g_wk[DMODEL * DMODEL];
__device__ __half g_wv[DMODEL * DMODEL];
__device__ __half g_wo[DMODEL * DMODEL];
__device__ __half g_q[MROWS * DMODEL];
__device__ __half g_k[MROWS * DMODEL];
__device__ __half g_v[MROWS * DMODEL];
__device__ __half g_ctx[MROWS * DMODEL];

// ---------------------------------------------------------------------------
// helpers
// ---------------------------------------------------------------------------
__device__ __forceinline__ uint32_t smem_u32(const void* p) {
    return (uint32_t)__cvta_generic_to_shared(p);
}
__device__ __forceinline__ void cp16(uint32_t s, const void* g) {
    asm volatile("cp.async.cg.shared.global [%0], [%1], 16;" :: "r"(s), "l"(g));
}
__device__ __forceinline__ void cp_commit() {
    asm volatile("cp.async.commit_group;");
}
template <int N>
__device__ __forceinline__ void cp_wait() {
    asm volatile("cp.async.wait_group %0;" :: "n"(N));
}
__device__ __forceinline__ void ldmx4(uint32_t& r0, uint32_t& r1, uint32_t& r2, uint32_t& r3,
                                      uint32_t addr) {
    asm volatile("ldmatrix.sync.aligned.m8n8.x4.shared.b16 {%0,%1,%2,%3}, [%4];"
                 : "=r"(r0), "=r"(r1), "=r"(r2), "=r"(r3) : "r"(addr));
}
__device__ __forceinline__ void ldmx4t(uint32_t& r0, uint32_t& r1, uint32_t& r2, uint32_t& r3,
                                       uint32_t addr) {
    asm volatile("ldmatrix.sync.aligned.m8n8.x4.trans.shared.b16 {%0,%1,%2,%3}, [%4];"
                 : "=r"(r0), "=r"(r1), "=r"(r2), "=r"(r3) : "r"(addr));
}
__device__ __forceinline__ void mma16816(float d[4], uint32_t a0, uint32_t a1, uint32_t a2,
                                         uint32_t a3, uint32_t b0, uint32_t b1) {
    asm volatile(
        "mma.sync.aligned.m16n8k16.row.col.f32.f16.f16.f32 "
        "{%0,%1,%2,%3},{%4,%5,%6,%7},{%8,%9},{%0,%1,%2,%3};"
        : "+f"(d[0]), "+f"(d[1]), "+f"(d[2]), "+f"(d[3])
        : "r"(a0), "r"(a1), "r"(a2), "r"(a3), "r"(b0), "r"(b1));
}
// pack two f32 into half2: lo = first arg, hi = second (PTX packs %1 -> hi)
__device__ __forceinline__ uint32_t cvt_h2(float lo, float hi) {
    uint32_t r;
    asm("cvt.rn.f16x2.f32 %0, %1, %2;" : "=r"(r) : "f"(hi), "f"(lo));
    return r;
}
// 2^x on a packed half2 (one MUFU op for two values)
__device__ __forceinline__ uint32_t ex2_h2(uint32_t x) {
    uint32_t r;
    asm("ex2.approx.f16x2 %0, %1;" : "=r"(r) : "r"(x));
    return r;
}

// ---------------------------------------------------------------------------
// fp32 -> fp16 conversion: single launch, blockIdx.y selects array.
// ---------------------------------------------------------------------------
__global__ __launch_bounds__(256) void cvt_f2h_all(
    const float* __restrict__ x,  const float* __restrict__ wq,
    const float* __restrict__ wk, const float* __restrict__ wv,
    const float* __restrict__ wo,
    __half* __restrict__ xh, __half* __restrict__ hq, __half* __restrict__ hk,
    __half* __restrict__ hv, __half* __restrict__ ho, int nx, int nw)
{
    const float* in; __half* out; int n;
    switch (blockIdx.y) {
        case 0: in = x;  out = xh; n = nx; break;
        case 1: in = wq; out = hq; n = nw; break;
        case 2: in = wk; out = hk; n = nw; break;
        case 3: in = wv; out = hv; n = nw; break;
        default: in = wo; out = ho; n = nw; break;
    }
    for (int i = (blockIdx.x * blockDim.x + threadIdx.x) * 8; i < n;
         i += gridDim.x * blockDim.x * 8) {
        float4 a = *(const float4*)(in + i);
        float4 b = *(const float4*)(in + i + 4);
        __half2 h[4];
        h[0] = __floats2half2_rn(a.x, a.y);
        h[1] = __floats2half2_rn(a.z, a.w);
        h[2] = __floats2half2_rn(b.x, b.y);
        h[3] = __floats2half2_rn(b.z, b.w);
        *(uint4*)(out + i) = *(uint4*)h;
    }
}

// ---------------------------------------------------------------------------
// GEMM core: C[m,n] = scale * sum_k A[m,k] * W[n,k]  (fp16 in, OutT out)
// Block 256x128x32, 512 thr = 16 warps (4m x 4n), warp tile 64x32 (unchanged
// per-warp mix/registers), 4-stage cp.async, one barrier per iteration.
// vs 128x128: -25% cp.async bytes per MAC, halved A re-reads from L2.
// ---------------------------------------------------------------------------
static constexpr int GPAD = 40;               // halves per 32-half row (+8 pad)
static constexpr int G_ATILE = 256 * GPAD;    // halves per A stage
static constexpr int G_BTILE = 128 * GPAD;    // halves per B stage
static constexpr int GSTAGES = 4;
static constexpr int GEMM_SMEM = GSTAGES * (G_ATILE + G_BTILE) * 2;   // 122880 B... no: (256+128)*40*2*4 = 122880? 384*40=15360 halves *2B =30720B *4 = 122880 B

template <typename OutT>
__device__ __forceinline__ void gemm_core(
    const __half* __restrict__ A, const __half* __restrict__ W,
    OutT* __restrict__ C, int m0, int n0, float scale, char* sm)
{
    constexpr int K = DMODEL, N = DMODEL, BK = 32;
    __half* As = (__half*)sm;
    __half* Bs = As + GSTAGES * G_ATILE;

    const int tid = threadIdx.x;
    const int lane = tid & 31, warp = tid >> 5;
    const int wm = (warp >> 2) * 64;    // 0,64,128,192
    const int wn = (warp & 3) * 32;     // 0,32,64,96

    const uint32_t sA = smem_u32(As);
    const uint32_t sB = smem_u32(Bs);

    // cp.async: A 1024 chunks (256 rows x 4), B 512 chunks (128 rows x 4)
    const int ldrow = tid >> 2;        // 0..127
    const int ldc   = (tid & 3) * 8;   // halves

    auto issue = [&](int kb, int s) {
        const int k0 = kb * BK;
#pragma unroll
        for (int t = 0; t < 2; t++) {
            int row = ldrow + t * 128;
            uint32_t off = (uint32_t)((s * 256 + row) * GPAD + ldc) * 2;
            cp16(sA + off, A + (size_t)(m0 + row) * K + k0 + ldc);
        }
        {
            uint32_t off = (uint32_t)((s * 128 + ldrow) * GPAD + ldc) * 2;
            cp16(sB + off, W + (size_t)(n0 + ldrow) * K + k0 + ldc);
        }
        cp_commit();
    };

    const int rowA = (lane & 7) + 8 * ((lane >> 3) & 1);
    const int colA = 8 * (lane >> 4);
    const int rowB = (lane & 7) + 8 * (lane >> 4);
    const int colB = 8 * ((lane >> 3) & 1);

    uint32_t aAddr[4], bAddr[2];
#pragma unroll
    for (int mt = 0; mt < 4; mt++)
        aAddr[mt] = smem_u32(&As[(wm + mt * 16 + rowA) * GPAD + colA]);
#pragma unroll
    for (int p = 0; p < 2; p++)
        bAddr[p] = smem_u32(&Bs[(wn + p * 16 + rowB) * GPAD + colB]);

    float acc[4][4][4];
#pragma unroll
    for (int mt = 0; mt < 4; mt++)
#pragma unroll
        for (int nt = 0; nt < 4; nt++)
#pragma unroll
            for (int e = 0; e < 4; e++) acc[mt][nt][e] = 0.0f;

    const int NITER = K / BK;   // 32
    issue(0, 0); issue(1, 1); issue(2, 2);

    for (int it = 0; it < NITER; it++) {
        if (it < NITER - 2)       cp_wait<2>();
        else if (it == NITER - 2) cp_wait<1>();
        else                      cp_wait<0>();
        __syncthreads();
        if (it + 3 < NITER) issue(it + 3, (it + 3) % GSTAGES);

        const int s = it % GSTAGES;
        const uint32_t aoff = (uint32_t)(s * G_ATILE) * 2;
        const uint32_t boff = (uint32_t)(s * G_BTILE) * 2;

        uint32_t af[2][4][4], bf[2][4][2];
#pragma unroll
        for (int ks = 0; ks < 2; ks++) {
#pragma unroll
            for (int mt = 0; mt < 4; mt++)
                ldmx4(af[ks][mt][0], af[ks][mt][1], af[ks][mt][2], af[ks][mt][3],
                      aAddr[mt] + aoff + ks * 32);
#pragma unroll
            for (int p = 0; p < 2; p++)
                ldmx4(bf[ks][2 * p][0], bf[ks][2 * p][1],
                      bf[ks][2 * p + 1][0], bf[ks][2 * p + 1][1],
                      bAddr[p] + boff + ks * 32);
        }
#pragma unroll
        for (int ks = 0; ks < 2; ks++)
#pragma unroll
            for (int mt = 0; mt < 4; mt++)
#pragma unroll
                for (int nt = 0; nt < 4; nt++)
                    mma16816(acc[mt][nt], af[ks][mt][0], af[ks][mt][1],
                             af[ks][mt][2], af[ks][mt][3],
                             bf[ks][nt][0], bf[ks][nt][1]);
    }

    const int g = lane >> 2, tg = lane & 3;
#pragma unroll
    for (int mt = 0; mt < 4; mt++) {
        int r0 = m0 + wm + mt * 16 + g;
#pragma unroll
        for (int nt = 0; nt < 4; nt++) {
            int c = n0 + wn + nt * 8 + 2 * tg;
            if constexpr (sizeof(OutT) == 2) {
                *(__half2*)((__half*)C + (size_t)r0 * N + c) =
                    __floats2half2_rn(acc[mt][nt][0] * scale, acc[mt][nt][1] * scale);
                *(__half2*)((__half*)C + (size_t)(r0 + 8) * N + c) =
                    __floats2half2_rn(acc[mt][nt][2] * scale, acc[mt][nt][3] * scale);
            } else {
                *(float2*)((float*)C + (size_t)r0 * N + c) =
                    make_float2(acc[mt][nt][0] * scale, acc[mt][nt][1] * scale);
                *(float2*)((float*)C + (size_t)(r0 + 8) * N + c) =
                    make_float2(acc[mt][nt][2] * scale, acc[mt][nt][3] * scale);
            }
        }
    }
}

// Fused Q/K/V projections: blockIdx.z selects weight/output/scale.
// Q scale folds 1/sqrt(dk) AND log2(e): softmax runs in exp2 domain.
__global__ __launch_bounds__(512, 1) void gemm_qkv(
    const __half* __restrict__ A,
    const __half* __restrict__ Wq, const __half* __restrict__ Wk,
    const __half* __restrict__ Wv,
    __half* __restrict__ q, __half* __restrict__ k, __half* __restrict__ v)
{
    extern __shared__ char sm[];
    const __half* W; __half* C; float scale;
    switch (blockIdx.z) {
        case 0:  W = Wq; C = q; scale = 0.125f * 1.44269504088896f; break;
        case 1:  W = Wk; C = k; scale = 1.0f;   break;
        default: W = Wv; C = v; scale = 1.0f;   break;
    }
    gemm_core<__half>(A, W, C, blockIdx.y * 256, blockIdx.x * 128, scale, sm);
}

// Single GEMM (output projection, fp32 out).
__global__ __launch_bounds__(512, 1) void gemm_single_f(
    const __half* __restrict__ A, const __half* __restrict__ W,
    float* __restrict__ C)
{
    extern __shared__ char sm[];
    gemm_core<float>(A, W, C, blockIdx.y * 256, blockIdx.x * 128, 1.0f, sm);
}

// ---------------------------------------------------------------------------
// Flash attention, fp16 in/out, register softmax in exp2 domain with
// ex2.approx.f16x2, 3-stage cp.async K/V, one barrier per tile, 2 CTAs/SM.
// grid=(SEQ/128, H, B), 256 thr = 8 warps. (unchanged from R11)
// ---------------------------------------------------------------------------
static constexpr int F_PAD = 72;             // halves per row (144B stride)
static constexpr int F_KVT = 64 * F_PAD;     // halves per K or V stage
static constexpr int FLASH_SMEM = (128 * F_PAD + 6 * F_KVT) * 2;   // 73728 B

__global__ __launch_bounds__(256, 2) void flash_attn_h(
    const __half* __restrict__ Q, const __half* __restrict__ K,
    const __half* __restrict__ V, __half* __restrict__ O)
{
    constexpr int BM = 128, BN = 64, PAD = F_PAD;
    constexpr int KVT = F_KVT;
    extern __shared__ __half fsm[];
    __half* Qs = fsm;                 // 128*PAD
    __half* Ks = Qs + 128 * PAD;      // 3 stages
    __half* Vs = Ks + 3 * KVT;        // 3 stages

    const int tid = threadIdx.x;
    const int lane = tid & 31, warp = tid >> 5;
    const int g = lane >> 2, tg = lane & 3;
    const int wm = warp * 16;
    const int q0 = blockIdx.x * BM;
    const int h = blockIdx.y;
    const int b = blockIdx.z;

    const __half* Qb = Q + (size_t)(b * SEQ + q0) * DMODEL + h * DHEAD;
    const __half* Kb = K + (size_t)(b * SEQ) * DMODEL + h * DHEAD;
    const __half* Vb = V + (size_t)(b * SEQ) * DMODEL + h * DHEAD;

    const uint32_t sK = smem_u32(Ks);
    const uint32_t sV = smem_u32(Vs);

    const int ldrow = tid >> 3;       // 0..31
    const int ldoff = (tid & 7) * 8;  // halves

    auto issue_kv = [&](int t, int s) {
#pragma unroll
        for (int tt = 0; tt < 2; tt++) {
            int row = ldrow + tt * 32;
            uint32_t off = (uint32_t)(s * KVT + row * PAD + ldoff) * 2;
            const size_t gofs = (size_t)(t * BN + row) * DMODEL + ldoff;
            cp16(sK + off, Kb + gofs);
            cp16(sV + off, Vb + gofs);
        }
        cp_commit();
    };

#pragma unroll
    for (int t = 0; t < 4; t++) {
        int c = tid + t * 256;
        int row = c >> 3;
        int off = (c & 7) * 8;
        *(uint4*)&Qs[row * PAD + off] = *(const uint4*)(Qb + (size_t)row * DMODEL + off);
    }
    issue_kv(0, 0);
    issue_kv(1, 1);
    __syncthreads();

    const int rowA = (lane & 7) + 8 * ((lane >> 3) & 1);
    const int colA = 8 * (lane >> 4);
    const int rowB = (lane & 7) + 8 * (lane >> 4);
    const int colB = 8 * ((lane >> 3) & 1);

    uint32_t qf[4][4];
#pragma unroll
    for (int j = 0; j < 4; j++)
        ldmx4(qf[j][0], qf[j][1], qf[j][2], qf[j][3],
              smem_u32(&Qs[(wm + rowA) * PAD + 16 * j + colA]));

    uint32_t kAddr[4], vAddr[4];
#pragma unroll
    for (int p = 0; p < 4; p++) {
        kAddr[p] = smem_u32(&Ks[(p * 16 + rowB) * PAD + colB]);
        vAddr[p] = smem_u32(&Vs[rowA * PAD + p * 16 + colA]);
    }

    float oacc[8][4];
#pragma unroll
    for (int nt = 0; nt < 8; nt++)
#pragma unroll
        for (int e = 0; e < 4; e++) oacc[nt][e] = 0.0f;
    float m0r = -INFINITY, m1r = -INFINITY, l0r = 0.0f, l1r = 0.0f;

    const int NT = SEQ / BN;   // 32
    for (int t = 0; t < NT; t++) {
        if (t < NT - 1) cp_wait<1>(); else cp_wait<0>();
        __syncthreads();
        if (t + 2 < NT) issue_kv(t + 2, (t + 2) % 3);

        const uint32_t soff = (uint32_t)((t % 3) * KVT) * 2;

        float sacc[8][4];
#pragma unroll
        for (int nt = 0; nt < 8; nt++)
#pragma unroll
            for (int e = 0; e < 4; e++) sacc[nt][e] = 0.0f;

#pragma unroll
        for (int j = 0; j < 4; j++) {
#pragma unroll
            for (int p = 0; p < 4; p++) {
                uint32_t b0, b1, b2, b3;
                ldmx4(b0, b1, b2, b3, kAddr[p] + soff + 32 * j);
                mma16816(sacc[2 * p],     qf[j][0], qf[j][1], qf[j][2], qf[j][3], b0, b1);
                mma16816(sacc[2 * p + 1], qf[j][0], qf[j][1], qf[j][2], qf[j][3], b2, b3);
            }
        }

        // softmax in exp2 domain (scores pre-scaled by log2e)
        float mx0 = -INFINITY, mx1 = -INFINITY;
#pragma unroll
        for (int nt = 0; nt < 8; nt++) {
            mx0 = fmaxf(mx0, fmaxf(sacc[nt][0], sacc[nt][1]));
            mx1 = fmaxf(mx1, fmaxf(sacc[nt][2], sacc[nt][3]));
        }
        mx0 = fmaxf(mx0, __shfl_xor_sync(0xffffffffu, mx0, 1));
        mx0 = fmaxf(mx0, __shfl_xor_sync(0xffffffffu, mx0, 2));
        mx1 = fmaxf(mx1, __shfl_xor_sync(0xffffffffu, mx1, 1));
        mx1 = fmaxf(mx1, __shfl_xor_sync(0xffffffffu, mx1, 2));

        float mn0 = fmaxf(m0r, mx0), mn1 = fmaxf(m1r, mx1);
        float a0 = exp2f(m0r - mn0), a1 = exp2f(m1r - mn1);
        m0r = mn0; m1r = mn1;

        float s0 = 0.0f, s1 = 0.0f;
        uint32_t ph[8][2];
#pragma unroll
        for (int nt = 0; nt < 8; nt++) {
            uint32_t h01 = cvt_h2(sacc[nt][0] - mn0, sacc[nt][1] - mn0);
            uint32_t h23 = cvt_h2(sacc[nt][2] - mn1, sacc[nt][3] - mn1);
            ph[nt][0] = ex2_h2(h01);
            ph[nt][1] = ex2_h2(h23);
            float2 f01 = __half22float2(*(__half2*)&ph[nt][0]);
            float2 f23 = __half22float2(*(__half2*)&ph[nt][1]);
            s0 += f01.x + f01.y;
            s1 += f23.x + f23.y;
        }
        s0 += __shfl_xor_sync(0xffffffffu, s0, 1);
        s0 += __shfl_xor_sync(0xffffffffu, s0, 2);
        s1 += __shfl_xor_sync(0xffffffffu, s1, 1);
        s1 += __shfl_xor_sync(0xffffffffu, s1, 2);
        l0r = l0r * a0 + s0;
        l1r = l1r * a1 + s1;

#pragma unroll
        for (int nt = 0; nt < 8; nt++) {
            oacc[nt][0] *= a0; oacc[nt][1] *= a0;
            oacc[nt][2] *= a1; oacc[nt][3] *= a1;
        }

#pragma unroll
        for (int j = 0; j < 4; j++) {
#pragma unroll
            for (int p = 0; p < 4; p++) {
                uint32_t v0, v1, v2, v3;
                ldmx4t(v0, v1, v2, v3, vAddr[p] + soff + 2304 * j);
                mma16816(oacc[2 * p],     ph[2 * j][0], ph[2 * j][1],
                         ph[2 * j + 1][0], ph[2 * j + 1][1], v0, v1);
                mma16816(oacc[2 * p + 1], ph[2 * j][0], ph[2 * j][1],
                         ph[2 * j + 1][0], ph[2 * j + 1][1], v2, v3);
            }
        }
    }

    float inv0 = 1.0f / l0r, inv1 = 1.0f / l1r;
    __half* Ob = O + (size_t)(b * SEQ + q0 + wm) * DMODEL + h * DHEAD;
#pragma unroll
    for (int nt = 0; nt < 8; nt++) {
        int c = nt * 8 + 2 * tg;
        *(__half2*)(Ob + (size_t)g * DMODEL + c) =
            __floats2half2_rn(oacc[nt][0] * inv0, oacc[nt][1] * inv0);
        *(__half2*)(Ob + (size_t)(g + 8) * DMODEL + c) =
            __floats2half2_rn(oacc[nt][2] * inv1, oacc[nt][3] * inv1);
    }
}

// ---------------------------------------------------------------------------

extern "C" void kernel_launch(void* const* d_in, const int* in_sizes, int n_in,
                              void* d_out, int out_size)
{
    const float* X  = (const float*)d_in[0];
    const float* Wq = (const float*)d_in[1];
    const float* Wk = (const float*)d_in[2];
    const float* Wv = (const float*)d_in[3];
    const float* Wo = (const float*)d_in[4];
    float* out = (float*)d_out;

    __half *xh, *wq, *wk, *wv, *wo, *q, *k, *v, *ctx;
    cudaGetSymbolAddress((void**)&xh, g_xh);
    cudaGetSymbolAddress((void**)&wq, g_wq);
    cudaGetSymbolAddress((void**)&wk, g_wk);
    cudaGetSymbolAddress((void**)&wv, g_wv);
    cudaGetSymbolAddress((void**)&wo, g_wo);
    cudaGetSymbolAddress((void**)&q,  g_q);
    cudaGetSymbolAddress((void**)&k,  g_k);
    cudaGetSymbolAddress((void**)&v,  g_v);
    cudaGetSymbolAddress((void**)&ctx, g_ctx);

    cudaFuncSetAttribute(gemm_qkv,      cudaFuncAttributeMaxDynamicSharedMemorySize, GEMM_SMEM);
    cudaFuncSetAttribute(gemm_single_f, cudaFuncAttributeMaxDynamicSharedMemorySize, GEMM_SMEM);
    cudaFuncSetAttribute(flash_attn_h,  cudaFuncAttributeMaxDynamicSharedMemorySize, FLASH_SMEM);

    const int NX = MROWS * DMODEL;      // 8.4M
    const int NW = DMODEL * DMODEL;     // 1.05M
    cvt_f2h_all<<<dim3(512, 5), 256>>>(X, Wq, Wk, Wv, Wo, xh, wq, wk, wv, wo, NX, NW);

    dim3 gqkv(DMODEL / 128, MROWS / 256, 3);    // (8, 32, 3)
    gemm_qkv<<<gqkv, 512, GEMM_SMEM>>>(xh, wq, wk, wv, q, k, v);

    dim3 gattn(SEQ / 128, NHEAD, BATCH);        // (16, 16, 4)
    flash_attn_h<<<gattn, 256, FLASH_SMEM>>>(q, k, v, ctx);

    dim3 gout(DMODEL / 128, MROWS / 256);       // (8, 32)
    gemm_single_f<<<gout, 512, GEMM_SMEM>>>(ctx, wo, out);
}

// round 13
// speedup vs baseline: 1.1406x; 1.1406x over previous
#include <cuda_runtime.h>
#include <cuda_fp16.h>
#include <math.h>
#include <stdint.h>

#define BATCH 4
#define SEQ   2048
#define DMODEL 1024
#define NHEAD 16
#define DHEAD 64
#define MROWS (BATCH * SEQ)   // 8192

// Scratch (device globals: allocation-free, graph-capture safe)
__device__ __half g_xh[MROWS * DMODEL];
__device__ __half g_wq[DMODEL * DMODEL];
__device__ __half g_wk[DMODEL * DMODEL];
__device__ __half g_wv[DMODEL * DMODEL];
__device__ __half g_wo[DMODEL * DMODEL];
__device__ __half g_q[MROWS * DMODEL];
__device__ __half g_k[MROWS * DMODEL];
__device__ __half g_v[MROWS * DMODEL];
__device__ __half g_ctx[MROWS * DMODEL];

// ---------------------------------------------------------------------------
// helpers
// ---------------------------------------------------------------------------
__device__ __forceinline__ uint32_t smem_u32(const void* p) {
    return (uint32_t)__cvta_generic_to_shared(p);
}
__device__ __forceinline__ void cp16(uint32_t s, const void* g) {
    asm volatile("cp.async.cg.shared.global [%0], [%1], 16;" :: "r"(s), "l"(g));
}
__device__ __forceinline__ void cp_commit() {
    asm volatile("cp.async.commit_group;");
}
template <int N>
__device__ __forceinline__ void cp_wait() {
    asm volatile("cp.async.wait_group %0;" :: "n"(N));
}
__device__ __forceinline__ void ldmx4(uint32_t& r0, uint32_t& r1, uint32_t& r2, uint32_t& r3,
                                      uint32_t addr) {
    asm volatile("ldmatrix.sync.aligned.m8n8.x4.shared.b16 {%0,%1,%2,%3}, [%4];"
                 : "=r"(r0), "=r"(r1), "=r"(r2), "=r"(r3) : "r"(addr));
}
__device__ __forceinline__ void ldmx4t(uint32_t& r0, uint32_t& r1, uint32_t& r2, uint32_t& r3,
                                       uint32_t addr) {
    asm volatile("ldmatrix.sync.aligned.m8n8.x4.trans.shared.b16 {%0,%1,%2,%3}, [%4];"
                 : "=r"(r0), "=r"(r1), "=r"(r2), "=r"(r3) : "r"(addr));
}
__device__ __forceinline__ void mma16816(float d[4], uint32_t a0, uint32_t a1, uint32_t a2,
                                         uint32_t a3, uint32_t b0, uint32_t b1) {
    asm volatile(
        "mma.sync.aligned.m16n8k16.row.col.f32.f16.f16.f32 "
        "{%0,%1,%2,%3},{%4,%5,%6,%7},{%8,%9},{%0,%1,%2,%3};"
        : "+f"(d[0]), "+f"(d[1]), "+f"(d[2]), "+f"(d[3])
        : "r"(a0), "r"(a1), "r"(a2), "r"(a3), "r"(b0), "r"(b1));
}
// pack two f32 into half2: lo = first arg, hi = second (PTX packs %1 -> hi)
__device__ __forceinline__ uint32_t cvt_h2(float lo, float hi) {
    uint32_t r;
    asm("cvt.rn.f16x2.f32 %0, %1, %2;" : "=r"(r) : "f"(hi), "f"(lo));
    return r;
}
// 2^x on a packed half2 (one MUFU op for two values)
__device__ __forceinline__ uint32_t ex2_h2(uint32_t x) {
    uint32_t r;
    asm("ex2.approx.f16x2 %0, %1;" : "=r"(r) : "r"(x));
    return r;
}

// ---------------------------------------------------------------------------
// fp32 -> fp16 conversion: single launch, blockIdx.y selects array.
// ---------------------------------------------------------------------------
__global__ __launch_bounds__(256) void cvt_f2h_all(
    const float* __restrict__ x,  const float* __restrict__ wq,
    const float* __restrict__ wk, const float* __restrict__ wv,
    const float* __restrict__ wo,
    __half* __restrict__ xh, __half* __restrict__ hq, __half* __restrict__ hk,
    __half* __restrict__ hv, __half* __restrict__ ho, int nx, int nw)
{
    const float* in; __half* out; int n;
    switch (blockIdx.y) {
        case 0: in = x;  out = xh; n = nx; break;
        case 1: in = wq; out = hq; n = nw; break;
        case 2: in = wk; out = hk; n = nw; break;
        case 3: in = wv; out = hv; n = nw; break;
        default: in = wo; out = ho; n = nw; break;
    }
    for (int i = (blockIdx.x * blockDim.x + threadIdx.x) * 8; i < n;
         i += gridDim.x * blockDim.x * 8) {
        float4 a = *(const float4*)(in + i);
        float4 b = *(const float4*)(in + i + 4);
        __half2 h[4];
        h[0] = __floats2half2_rn(a.x, a.y);
        h[1] = __floats2half2_rn(a.z, a.w);
        h[2] = __floats2half2_rn(b.x, b.y);
        h[3] = __floats2half2_rn(b.z, b.w);
        *(uint4*)(out + i) = *(uint4*)h;
    }
}

// ---------------------------------------------------------------------------
// GEMM core: C[m,n] = scale * sum_k A[m,k] * W[n,k]  (fp16 in, OutT out)
// Block 128x128x32, 256 thr = 8 warps (2m x 4n), warp tile 64x32, 4-stage
// cp.async, 2 CTAs/SM, one barrier per iteration, k-step register
// double-buffer: mma(ksX) trails load(ksX) by 16 MMAs so LDSM latency
// (incl. post-barrier) is always covered. Accum order per chunk unchanged.
// ---------------------------------------------------------------------------
static constexpr int GPAD = 40;              // halves per 32-half row (+8 pad)
static constexpr int G_TILE = 128 * GPAD;    // halves per stage per matrix
static constexpr int GSTAGES = 4;
static constexpr int GEMM_SMEM = GSTAGES * 2 * G_TILE * 2;   // 81920 B

template <typename OutT>
__device__ __forceinline__ void gemm_core(
    const __half* __restrict__ A, const __half* __restrict__ W,
    OutT* __restrict__ C, int m0, int n0, float scale, char* sm)
{
    constexpr int K = DMODEL, N = DMODEL, BK = 32;
    __half* As = (__half*)sm;
    __half* Bs = As + GSTAGES * G_TILE;

    const int tid = threadIdx.x;
    const int lane = tid & 31, warp = tid >> 5;
    const int wm = (warp >> 2) * 64;    // 0,64
    const int wn = (warp & 3) * 32;     // 0,32,64,96

    const uint32_t sA = smem_u32(As);
    const uint32_t sB = smem_u32(Bs);

    const int ldrow = tid >> 2;        // 0..63
    const int ldc   = (tid & 3) * 8;   // halves

    auto issue = [&](int kb, int s) {
        const int k0 = kb * BK;
#pragma unroll
        for (int t = 0; t < 2; t++) {
            int row = ldrow + t * 64;
            uint32_t off = (uint32_t)((s * 128 + row) * GPAD + ldc) * 2;
            cp16(sA + off, A + (size_t)(m0 + row) * K + k0 + ldc);
            cp16(sB + off, W + (size_t)(n0 + row) * K + k0 + ldc);
        }
        cp_commit();
    };

    const int rowA = (lane & 7) + 8 * ((lane >> 3) & 1);
    const int colA = 8 * (lane >> 4);
    const int rowB = (lane & 7) + 8 * (lane >> 4);
    const int colB = 8 * ((lane >> 3) & 1);

    uint32_t aAddr[4], bAddr[2];
#pragma unroll
    for (int mt = 0; mt < 4; mt++)
        aAddr[mt] = smem_u32(&As[(wm + mt * 16 + rowA) * GPAD + colA]);
#pragma unroll
    for (int p = 0; p < 2; p++)
        bAddr[p] = smem_u32(&Bs[(wn + p * 16 + rowB) * GPAD + colB]);

    float acc[4][4][4];
#pragma unroll
    for (int mt = 0; mt < 4; mt++)
#pragma unroll
        for (int nt = 0; nt < 4; nt++)
#pragma unroll
            for (int e = 0; e < 4; e++) acc[mt][nt][e] = 0.0f;

    // two fragment buffers (same register budget as before)
    uint32_t af[2][4][4], bf[2][4][2];

    auto load_frags = [&](int buf, uint32_t soff, int ks) {
#pragma unroll
        for (int mt = 0; mt < 4; mt++)
            ldmx4(af[buf][mt][0], af[buf][mt][1], af[buf][mt][2], af[buf][mt][3],
                  aAddr[mt] + soff + ks * 32);
#pragma unroll
        for (int p = 0; p < 2; p++)
            ldmx4(bf[buf][2 * p][0], bf[buf][2 * p][1],
                  bf[buf][2 * p + 1][0], bf[buf][2 * p + 1][1],
                  bAddr[p] + soff + ks * 32);
    };
    auto mma_frags = [&](int buf) {
#pragma unroll
        for (int mt = 0; mt < 4; mt++)
#pragma unroll
            for (int nt = 0; nt < 4; nt++)
                mma16816(acc[mt][nt], af[buf][mt][0], af[buf][mt][1],
                         af[buf][mt][2], af[buf][mt][3],
                         bf[buf][nt][0], bf[buf][nt][1]);
    };

    const int NITER = K / BK;   // 32
    issue(0, 0); issue(1, 1); issue(2, 2);

    for (int it = 0; it < NITER; it++) {
        if (it < NITER - 2)       cp_wait<2>();
        else if (it == NITER - 2) cp_wait<1>();
        else                      cp_wait<0>();
        __syncthreads();
        if (it + 3 < NITER) issue(it + 3, (it + 3) % GSTAGES);

        const uint32_t soff = (uint32_t)((it % GSTAGES) * G_TILE) * 2;

        load_frags(0, soff, 0);      // ks0 of chunk it
        if (it > 0) mma_frags(1);    // ks1 of chunk it-1 (loaded last iter)
        load_frags(1, soff, 1);      // ks1 of chunk it
        mma_frags(0);                // ks0 of chunk it
    }
    mma_frags(1);                    // ks1 of final chunk

    const int g = lane >> 2, tg = lane & 3;
#pragma unroll
    for (int mt = 0; mt < 4; mt++) {
        int r0 = m0 + wm + mt * 16 + g;
#pragma unroll
        for (int nt = 0; nt < 4; nt++) {
            int c = n0 + wn + nt * 8 + 2 * tg;
            if constexpr (sizeof(OutT) == 2) {
                *(__half2*)((__half*)C + (size_t)r0 * N + c) =
                    __floats2half2_rn(acc[mt][nt][0] * scale, acc[mt][nt][1] * scale);
                *(__half2*)((__half*)C + (size_t)(r0 + 8) * N + c) =
                    __floats2half2_rn(acc[mt][nt][2] * scale, acc[mt][nt][3] * scale);
            } else {
                *(float2*)((float*)C + (size_t)r0 * N + c) =
                    make_float2(acc[mt][nt][0] * scale, acc[mt][nt][1] * scale);
                *(float2*)((float*)C + (size_t)(r0 + 8) * N + c) =
                    make_float2(acc[mt][nt][2] * scale, acc[mt][nt][3] * scale);
            }
        }
    }
}

// Fused Q/K/V projections: blockIdx.z selects weight/output/scale.
// Q scale folds 1/sqrt(dk) AND log2(e): softmax runs in exp2 domain.
__global__ __launch_bounds__(256, 2) void gemm_qkv(
    const __half* __restrict__ A,
    const __half* __restrict__ Wq, const __half* __restrict__ Wk,
    const __half* __restrict__ Wv,
    __half* __restrict__ q, __half* __restrict__ k, __half* __restrict__ v)
{
    extern __shared__ char sm[];
    const __half* W; __half* C; float scale;
    switch (blockIdx.z) {
        case 0:  W = Wq; C = q; scale = 0.125f * 1.44269504088896f; break;
        case 1:  W = Wk; C = k; scale = 1.0f;   break;
        default: W = Wv; C = v; scale = 1.0f;   break;
    }
    gemm_core<__half>(A, W, C, blockIdx.y * 128, blockIdx.x * 128, scale, sm);
}

// Single GEMM (output projection, fp32 out).
__global__ __launch_bounds__(256, 2) void gemm_single_f(
    const __half* __restrict__ A, const __half* __restrict__ W,
    float* __restrict__ C)
{
    extern __shared__ char sm[];
    gemm_core<float>(A, W, C, blockIdx.y * 128, blockIdx.x * 128, 1.0f, sm);
}

// ---------------------------------------------------------------------------
// Flash attention, fp16 in/out, register softmax in exp2 domain with
// ex2.approx.f16x2, 3-stage cp.async K/V, one barrier per tile, 2 CTAs/SM.
// grid=(SEQ/128, H, B), 256 thr = 8 warps. (unchanged from R11)
// ---------------------------------------------------------------------------
static constexpr int F_PAD = 72;             // halves per row (144B stride)
static constexpr int F_KVT = 64 * F_PAD;     // halves per K or V stage
static constexpr int FLASH_SMEM = (128 * F_PAD + 6 * F_KVT) * 2;   // 73728 B

__global__ __launch_bounds__(256, 2) void flash_attn_h(
    const __half* __restrict__ Q, const __half* __restrict__ K,
    const __half* __restrict__ V, __half* __restrict__ O)
{
    constexpr int BM = 128, BN = 64, PAD = F_PAD;
    constexpr int KVT = F_KVT;
    extern __shared__ __half fsm[];
    __half* Qs = fsm;                 // 128*PAD
    __half* Ks = Qs + 128 * PAD;      // 3 stages
    __half* Vs = Ks + 3 * KVT;        // 3 stages

    const int tid = threadIdx.x;
    const int lane = tid & 31, warp = tid >> 5;
    const int g = lane >> 2, tg = lane & 3;
    const int wm = warp * 16;
    const int q0 = blockIdx.x * BM;
    const int h = blockIdx.y;
    const int b = blockIdx.z;

    const __half* Qb = Q + (size_t)(b * SEQ + q0) * DMODEL + h * DHEAD;
    const __half* Kb = K + (size_t)(b * SEQ) * DMODEL + h * DHEAD;
    const __half* Vb = V + (size_t)(b * SEQ) * DMODEL + h * DHEAD;

    const uint32_t sK = smem_u32(Ks);
    const uint32_t sV = smem_u32(Vs);

    const int ldrow = tid >> 3;       // 0..31
    const int ldoff = (tid & 7) * 8;  // halves

    auto issue_kv = [&](int t, int s) {
#pragma unroll
        for (int tt = 0; tt < 2; tt++) {
            int row = ldrow + tt * 32;
            uint32_t off = (uint32_t)(s * KVT + row * PAD + ldoff) * 2;
            const size_t gofs = (size_t)(t * BN + row) * DMODEL + ldoff;
            cp16(sK + off, Kb + gofs);
            cp16(sV + off, Vb + gofs);
        }
        cp_commit();
    };

#pragma unroll
    for (int t = 0; t < 4; t++) {
        int c = tid + t * 256;
        int row = c >> 3;
        int off = (c & 7) * 8;
        *(uint4*)&Qs[row * PAD + off] = *(const uint4*)(Qb + (size_t)row * DMODEL + off);
    }
    issue_kv(0, 0);
    issue_kv(1, 1);
    __syncthreads();

    const int rowA = (lane & 7) + 8 * ((lane >> 3) & 1);
    const int colA = 8 * (lane >> 4);
    const int rowB = (lane & 7) + 8 * (lane >> 4);
    const int colB = 8 * ((lane >> 3) & 1);

    uint32_t qf[4][4];
#pragma unroll
    for (int j = 0; j < 4; j++)
        ldmx4(qf[j][0], qf[j][1], qf[j][2], qf[j][3],
              smem_u32(&Qs[(wm + rowA) * PAD + 16 * j + colA]));

    uint32_t kAddr[4], vAddr[4];
#pragma unroll
    for (int p = 0; p < 4; p++) {
        kAddr[p] = smem_u32(&Ks[(p * 16 + rowB) * PAD + colB]);
        vAddr[p] = smem_u32(&Vs[rowA * PAD + p * 16 + colA]);
    }

    float oacc[8][4];
#pragma unroll
    for (int nt = 0; nt < 8; nt++)
#pragma unroll
        for (int e = 0; e < 4; e++) oacc[nt][e] = 0.0f;
    float m0r = -INFINITY, m1r = -INFINITY, l0r = 0.0f, l1r = 0.0f;

    const int NT = SEQ / BN;   // 32
    for (int t = 0; t < NT; t++) {
        if (t < NT - 1) cp_wait<1>(); else cp_wait<0>();
        __syncthreads();
        if (t + 2 < NT) issue_kv(t + 2, (t + 2) % 3);

        const uint32_t soff = (uint32_t)((t % 3) * KVT) * 2;

        float sacc[8][4];
#pragma unroll
        for (int nt = 0; nt < 8; nt++)
#pragma unroll
            for (int e = 0; e < 4; e++) sacc[nt][e] = 0.0f;

#pragma unroll
        for (int j = 0; j < 4; j++) {
#pragma unroll
            for (int p = 0; p < 4; p++) {
                uint32_t b0, b1, b2, b3;
                ldmx4(b0, b1, b2, b3, kAddr[p] + soff + 32 * j);
                mma16816(sacc[2 * p],     qf[j][0], qf[j][1], qf[j][2], qf[j][3], b0, b1);
                mma16816(sacc[2 * p + 1], qf[j][0], qf[j][1], qf[j][2], qf[j][3], b2, b3);
            }
        }

        // softmax in exp2 domain (scores pre-scaled by log2e)
        float mx0 = -INFINITY, mx1 = -INFINITY;
#pragma unroll
        for (int nt = 0; nt < 8; nt++) {
            mx0 = fmaxf(mx0, fmaxf(sacc[nt][0], sacc[nt][1]));
            mx1 = fmaxf(mx1, fmaxf(sacc[nt][2], sacc[nt][3]));
        }
        mx0 = fmaxf(mx0, __shfl_xor_sync(0xffffffffu, mx0, 1));
        mx0 = fmaxf(mx0, __shfl_xor_sync(0xffffffffu, mx0, 2));
        mx1 = fmaxf(mx1, __shfl_xor_sync(0xffffffffu, mx1, 1));
        mx1 = fmaxf(mx1, __shfl_xor_sync(0xffffffffu, mx1, 2));

        float mn0 = fmaxf(m0r, mx0), mn1 = fmaxf(m1r, mx1);
        float a0 = exp2f(m0r - mn0), a1 = exp2f(m1r - mn1);
        m0r = mn0; m1r = mn1;

        float s0 = 0.0f, s1 = 0.0f;
        uint32_t ph[8][2];
#pragma unroll
        for (int nt = 0; nt < 8; nt++) {
            uint32_t h01 = cvt_h2(sacc[nt][0] - mn0, sacc[nt][1] - mn0);
            uint32_t h23 = cvt_h2(sacc[nt][2] - mn1, sacc[nt][3] - mn1);
            ph[nt][0] = ex2_h2(h01);
            ph[nt][1] = ex2_h2(h23);
            float2 f01 = __half22float2(*(__half2*)&ph[nt][0]);
            float2 f23 = __half22float2(*(__half2*)&ph[nt][1]);
            s0 += f01.x + f01.y;
            s1 += f23.x + f23.y;
        }
        s0 += __shfl_xor_sync(0xffffffffu, s0, 1);
        s0 += __shfl_xor_sync(0xffffffffu, s0, 2);
        s1 += __shfl_xor_sync(0xffffffffu, s1, 1);
        s1 += __shfl_xor_sync(0xffffffffu, s1, 2);
        l0r = l0r * a0 + s0;
        l1r = l1r * a1 + s1;

#pragma unroll
        for (int nt = 0; nt < 8; nt++) {
            oacc[nt][0] *= a0; oacc[nt][1] *= a0;
            oacc[nt][2] *= a1; oacc[nt][3] *= a1;
        }

#pragma unroll
        for (int j = 0; j < 4; j++) {
#pragma unroll
            for (int p = 0; p < 4; p++) {
                uint32_t v0, v1, v2, v3;
                ldmx4t(v0, v1, v2, v3, vAddr[p] + soff + 2304 * j);
                mma16816(oacc[2 * p],     ph[2 * j][0], ph[2 * j][1],
                         ph[2 * j + 1][0], ph[2 * j + 1][1], v0, v1);
                mma16816(oacc[2 * p + 1], ph[2 * j][0], ph[2 * j][1],
                         ph[2 * j + 1][0], ph[2 * j + 1][1], v2, v3);
            }
        }
    }

    float inv0 = 1.0f / l0r, inv1 = 1.0f / l1r;
    __half* Ob = O + (size_t)(b * SEQ + q0 + wm) * DMODEL + h * DHEAD;
#pragma unroll
    for (int nt = 0; nt < 8; nt++) {
        int c = nt * 8 + 2 * tg;
        *(__half2*)(Ob + (size_t)g * DMODEL + c) =
            __floats2half2_rn(oacc[nt][0] * inv0, oacc[nt][1] * inv0);
        *(__half2*)(Ob + (size_t)(g + 8) * DMODEL + c) =
            __floats2half2_rn(oacc[nt][2] * inv1, oacc[nt][3] * inv1);
    }
}

// ---------------------------------------------------------------------------

extern "C" void kernel_launch(void* const* d_in, const int* in_sizes, int n_in,
                              void* d_out, int out_size)
{
    const float* X  = (const float*)d_in[0];
    const float* Wq = (const float*)d_in[1];
    const float* Wk = (const float*)d_in[2];
    const float* Wv = (const float*)d_in[3];
    const float* Wo = (const float*)d_in[4];
    float* out = (float*)d_out;

    __half *xh, *wq, *wk, *wv, *wo, *q, *k, *v, *ctx;
    cudaGetSymbolAddress((void**)&xh, g_xh);
    cudaGetSymbolAddress((void**)&wq, g_wq);
    cudaGetSymbolAddress((void**)&wk, g_wk);
    cudaGetSymbolAddress((void**)&wv, g_wv);
    cudaGetSymbolAddress((void**)&wo, g_wo);
    cudaGetSymbolAddress((void**)&q,  g_q);
    cudaGetSymbolAddress((void**)&k,  g_k);
    cudaGetSymbolAddress((void**)&v,  g_v);
    cudaGetSymbolAddress((void**)&ctx, g_ctx);

    cudaFuncSetAttribute(gemm_qkv,      cudaFuncAttributeMaxDynamicSharedMemorySize, GEMM_SMEM);
    cudaFuncSetAttribute(gemm_single_f, cudaFuncAttributeMaxDynamicSharedMemorySize, GEMM_SMEM);
    cudaFuncSetAttribute(flash_attn_h,  cudaFuncAttributeMaxDynamicSharedMemorySize, FLASH_SMEM);

    const int NX = MROWS * DMODEL;      // 8.4M
    const int NW = DMODEL * DMODEL;     // 1.05M
    cvt_f2h_all<<<dim3(2048, 5), 256>>>(X, Wq, Wk, Wv, Wo, xh, wq, wk, wv, wo, NX, NW);

    dim3 gqkv(DMODEL / 128, MROWS / 128, 3);    // (8, 64, 3)
    gemm_qkv<<<gqkv, 256, GEMM_SMEM>>>(xh, wq, wk, wv, q, k, v);

    dim3 gattn(SEQ / 128, NHEAD, BATCH);        // (16, 16, 4)
    flash_attn_h<<<gattn, 256, FLASH_SMEM>>>(q, k, v, ctx);

    dim3 gout(DMODEL / 128, MROWS / 128);       // (8, 64)
    gemm_single_f<<<gout, 256, GEMM_SMEM>>>(ctx, wo, out);
}

// round 14
// speedup vs baseline: 1.1452x; 1.0040x over previous
#include <cuda_runtime.h>
#include <cuda_fp16.h>
#include <math.h>
#include <stdint.h>

#define BATCH 4
#define SEQ   2048
#define DMODEL 1024
#define NHEAD 16
#define DHEAD 64
#define MROWS (BATCH * SEQ)   // 8192

// Scratch (device globals: allocation-free, graph-capture safe)
__device__ __half g_xh[MROWS * DMODEL];
__device__ __half g_wq[DMODEL * DMODEL];
__device__ __half g_wk[DMODEL * DMODEL];
__device__ __half g_wv[DMODEL * DMODEL];
__device__ __half g_wo[DMODEL * DMODEL];
__device__ __half g_q[MROWS * DMODEL];
__device__ __half g_k[MROWS * DMODEL];
__device__ __half g_v[MROWS * DMODEL];
__device__ __half g_ctx[MROWS * DMODEL];

// ---------------------------------------------------------------------------
// helpers
// ---------------------------------------------------------------------------
__device__ __forceinline__ uint32_t smem_u32(const void* p) {
    return (uint32_t)__cvta_generic_to_shared(p);
}
__device__ __forceinline__ void cp16(uint32_t s, const void* g) {
    asm volatile("cp.async.cg.shared.global [%0], [%1], 16;" :: "r"(s), "l"(g));
}
__device__ __forceinline__ void cp_commit() {
    asm volatile("cp.async.commit_group;");
}
template <int N>
__device__ __forceinline__ void cp_wait() {
    asm volatile("cp.async.wait_group %0;" :: "n"(N));
}
__device__ __forceinline__ void ldmx4(uint32_t& r0, uint32_t& r1, uint32_t& r2, uint32_t& r3,
                                      uint32_t addr) {
    asm volatile("ldmatrix.sync.aligned.m8n8.x4.shared.b16 {%0,%1,%2,%3}, [%4];"
                 : "=r"(r0), "=r"(r1), "=r"(r2), "=r"(r3) : "r"(addr));
}
__device__ __forceinline__ void ldmx4t(uint32_t& r0, uint32_t& r1, uint32_t& r2, uint32_t& r3,
                                       uint32_t addr) {
    asm volatile("ldmatrix.sync.aligned.m8n8.x4.trans.shared.b16 {%0,%1,%2,%3}, [%4];"
                 : "=r"(r0), "=r"(r1), "=r"(r2), "=r"(r3) : "r"(addr));
}
__device__ __forceinline__ void mma16816(float d[4], uint32_t a0, uint32_t a1, uint32_t a2,
                                         uint32_t a3, uint32_t b0, uint32_t b1) {
    asm volatile(
        "mma.sync.aligned.m16n8k16.row.col.f32.f16.f16.f32 "
        "{%0,%1,%2,%3},{%4,%5,%6,%7},{%8,%9},{%0,%1,%2,%3};"
        : "+f"(d[0]), "+f"(d[1]), "+f"(d[2]), "+f"(d[3])
        : "r"(a0), "r"(a1), "r"(a2), "r"(a3), "r"(b0), "r"(b1));
}
// pack two f32 into half2: lo = first arg, hi = second (PTX packs %1 -> hi)
__device__ __forceinline__ uint32_t cvt_h2(float lo, float hi) {
    uint32_t r;
    asm("cvt.rn.f16x2.f32 %0, %1, %2;" : "=r"(r) : "f"(hi), "f"(lo));
    return r;
}
// 2^x on a packed half2 (one MUFU op for two values)
__device__ __forceinline__ uint32_t ex2_h2(uint32_t x) {
    uint32_t r;
    asm("ex2.approx.f16x2 %0, %1;" : "=r"(r) : "r"(x));
    return r;
}

// ---------------------------------------------------------------------------
// fp32 -> fp16 conversion: single launch, blockIdx.y selects array.
// ---------------------------------------------------------------------------
__global__ __launch_bounds__(256) void cvt_f2h_all(
    const float* __restrict__ x,  const float* __restrict__ wq,
    const float* __restrict__ wk, const float* __restrict__ wv,
    const float* __restrict__ wo,
    __half* __restrict__ xh, __half* __restrict__ hq, __half* __restrict__ hk,
    __half* __restrict__ hv, __half* __restrict__ ho, int nx, int nw)
{
    const float* in; __half* out; int n;
    switch (blockIdx.y) {
        case 0: in = x;  out = xh; n = nx; break;
        case 1: in = wq; out = hq; n = nw; break;
        case 2: in = wk; out = hk; n = nw; break;
        case 3: in = wv; out = hv; n = nw; break;
        default: in = wo; out = ho; n = nw; break;
    }
    for (int i = (blockIdx.x * blockDim.x + threadIdx.x) * 8; i < n;
         i += gridDim.x * blockDim.x * 8) {
        float4 a = *(const float4*)(in + i);
        float4 b = *(const float4*)(in + i + 4);
        __half2 h[4];
        h[0] = __floats2half2_rn(a.x, a.y);
        h[1] = __floats2half2_rn(a.z, a.w);
        h[2] = __floats2half2_rn(b.x, b.y);
        h[3] = __floats2half2_rn(b.z, b.w);
        *(uint4*)(out + i) = *(uint4*)h;
    }
}

// ---------------------------------------------------------------------------
// GEMM core: C[m,n] = scale * sum_k A[m,k] * W[n,k]  (fp16 in, OutT out)
// Block 128x128x32, 256 thr = 8 warps (2m x 4n), warp tile 64x32, 4-stage
// cp.async, 2 CTAs/SM, one barrier per iteration, k-step register
// double-buffer. (unchanged from R13 winning version)
// ---------------------------------------------------------------------------
static constexpr int GPAD = 40;              // halves per 32-half row (+8 pad)
static constexpr int G_TILE = 128 * GPAD;    // halves per stage per matrix
static constexpr int GSTAGES = 4;
static constexpr int GEMM_SMEM = GSTAGES * 2 * G_TILE * 2;   // 81920 B

template <typename OutT>
__device__ __forceinline__ void gemm_core(
    const __half* __restrict__ A, const __half* __restrict__ W,
    OutT* __restrict__ C, int m0, int n0, float scale, char* sm)
{
    constexpr int K = DMODEL, N = DMODEL, BK = 32;
    __half* As = (__half*)sm;
    __half* Bs = As + GSTAGES * G_TILE;

    const int tid = threadIdx.x;
    const int lane = tid & 31, warp = tid >> 5;
    const int wm = (warp >> 2) * 64;    // 0,64
    const int wn = (warp & 3) * 32;     // 0,32,64,96

    const uint32_t sA = smem_u32(As);
    const uint32_t sB = smem_u32(Bs);

    const int ldrow = tid >> 2;        // 0..63
    const int ldc   = (tid & 3) * 8;   // halves

    auto issue = [&](int kb, int s) {
        const int k0 = kb * BK;
#pragma unroll
        for (int t = 0; t < 2; t++) {
            int row = ldrow + t * 64;
            uint32_t off = (uint32_t)((s * 128 + row) * GPAD + ldc) * 2;
            cp16(sA + off, A + (size_t)(m0 + row) * K + k0 + ldc);
            cp16(sB + off, W + (size_t)(n0 + row) * K + k0 + ldc);
        }
        cp_commit();
    };

    const int rowA = (lane & 7) + 8 * ((lane >> 3) & 1);
    const int colA = 8 * (lane >> 4);
    const int rowB = (lane & 7) + 8 * (lane >> 4);
    const int colB = 8 * ((lane >> 3) & 1);

    uint32_t aAddr[4], bAddr[2];
#pragma unroll
    for (int mt = 0; mt < 4; mt++)
        aAddr[mt] = smem_u32(&As[(wm + mt * 16 + rowA) * GPAD + colA]);
#pragma unroll
    for (int p = 0; p < 2; p++)
        bAddr[p] = smem_u32(&Bs[(wn + p * 16 + rowB) * GPAD + colB]);

    float acc[4][4][4];
#pragma unroll
    for (int mt = 0; mt < 4; mt++)
#pragma unroll
        for (int nt = 0; nt < 4; nt++)
#pragma unroll
            for (int e = 0; e < 4; e++) acc[mt][nt][e] = 0.0f;

    uint32_t af[2][4][4], bf[2][4][2];

    auto load_frags = [&](int buf, uint32_t soff, int ks) {
#pragma unroll
        for (int mt = 0; mt < 4; mt++)
            ldmx4(af[buf][mt][0], af[buf][mt][1], af[buf][mt][2], af[buf][mt][3],
                  aAddr[mt] + soff + ks * 32);
#pragma unroll
        for (int p = 0; p < 2; p++)
            ldmx4(bf[buf][2 * p][0], bf[buf][2 * p][1],
                  bf[buf][2 * p + 1][0], bf[buf][2 * p + 1][1],
                  bAddr[p] + soff + ks * 32);
    };
    auto mma_frags = [&](int buf) {
#pragma unroll
        for (int mt = 0; mt < 4; mt++)
#pragma unroll
            for (int nt = 0; nt < 4; nt++)
                mma16816(acc[mt][nt], af[buf][mt][0], af[buf][mt][1],
                         af[buf][mt][2], af[buf][mt][3],
                         bf[buf][nt][0], bf[buf][nt][1]);
    };

    const int NITER = K / BK;   // 32
    issue(0, 0); issue(1, 1); issue(2, 2);

    for (int it = 0; it < NITER; it++) {
        if (it < NITER - 2)       cp_wait<2>();
        else if (it == NITER - 2) cp_wait<1>();
        else                      cp_wait<0>();
        __syncthreads();
        if (it + 3 < NITER) issue(it + 3, (it + 3) % GSTAGES);

        const uint32_t soff = (uint32_t)((it % GSTAGES) * G_TILE) * 2;

        load_frags(0, soff, 0);      // ks0 of chunk it
        if (it > 0) mma_frags(1);    // ks1 of chunk it-1 (loaded last iter)
        load_frags(1, soff, 1);      // ks1 of chunk it
        mma_frags(0);                // ks0 of chunk it
    }
    mma_frags(1);                    // ks1 of final chunk

    const int g = lane >> 2, tg = lane & 3;
#pragma unroll
    for (int mt = 0; mt < 4; mt++) {
        int r0 = m0 + wm + mt * 16 + g;
#pragma unroll
        for (int nt = 0; nt < 4; nt++) {
            int c = n0 + wn + nt * 8 + 2 * tg;
            if constexpr (sizeof(OutT) == 2) {
                *(__half2*)((__half*)C + (size_t)r0 * N + c) =
                    __floats2half2_rn(acc[mt][nt][0] * scale, acc[mt][nt][1] * scale);
                *(__half2*)((__half*)C + (size_t)(r0 + 8) * N + c) =
                    __floats2half2_rn(acc[mt][nt][2] * scale, acc[mt][nt][3] * scale);
            } else {
                *(float2*)((float*)C + (size_t)r0 * N + c) =
                    make_float2(acc[mt][nt][0] * scale, acc[mt][nt][1] * scale);
                *(float2*)((float*)C + (size_t)(r0 + 8) * N + c) =
                    make_float2(acc[mt][nt][2] * scale, acc[mt][nt][3] * scale);
            }
        }
    }
}

// Fused Q/K/V projections: blockIdx.z selects weight/output/scale.
// Q scale folds 1/sqrt(dk) AND log2(e): softmax runs in exp2 domain.
__global__ __launch_bounds__(256, 2) void gemm_qkv(
    const __half* __restrict__ A,
    const __half* __restrict__ Wq, const __half* __restrict__ Wk,
    const __half* __restrict__ Wv,
    __half* __restrict__ q, __half* __restrict__ k, __half* __restrict__ v)
{
    extern __shared__ char sm[];
    const __half* W; __half* C; float scale;
    switch (blockIdx.z) {
        case 0:  W = Wq; C = q; scale = 0.125f * 1.44269504088896f; break;
        case 1:  W = Wk; C = k; scale = 1.0f;   break;
        default: W = Wv; C = v; scale = 1.0f;   break;
    }
    gemm_core<__half>(A, W, C, blockIdx.y * 128, blockIdx.x * 128, scale, sm);
}

// Single GEMM (output projection, fp32 out).
__global__ __launch_bounds__(256, 2) void gemm_single_f(
    const __half* __restrict__ A, const __half* __restrict__ W,
    float* __restrict__ C)
{
    extern __shared__ char sm[];
    gemm_core<float>(A, W, C, blockIdx.y * 128, blockIdx.x * 128, 1.0f, sm);
}

// ---------------------------------------------------------------------------
// Flash attention, fp16 in/out, register softmax in exp2 domain, 3-stage
// cp.async K/V, one barrier per tile, 2 CTAs/SM. QK^T and P.V inner loops
// are depth-1 software-pipelined (load frag kk+1 while issuing MMAs of kk)
// -- same trick that won R13 in the GEMM. MMA order unchanged.
// ---------------------------------------------------------------------------
static constexpr int F_PAD = 72;             // halves per row (144B stride)
static constexpr int F_KVT = 64 * F_PAD;     // halves per K or V stage
static constexpr int FLASH_SMEM = (128 * F_PAD + 6 * F_KVT) * 2;   // 73728 B

__global__ __launch_bounds__(256, 2) void flash_attn_h(
    const __half* __restrict__ Q, const __half* __restrict__ K,
    const __half* __restrict__ V, __half* __restrict__ O)
{
    constexpr int BM = 128, BN = 64, PAD = F_PAD;
    constexpr int KVT = F_KVT;
    extern __shared__ __half fsm[];
    __half* Qs = fsm;                 // 128*PAD
    __half* Ks = Qs + 128 * PAD;      // 3 stages
    __half* Vs = Ks + 3 * KVT;        // 3 stages

    const int tid = threadIdx.x;
    const int lane = tid & 31, warp = tid >> 5;
    const int g = lane >> 2, tg = lane & 3;
    const int wm = warp * 16;
    const int q0 = blockIdx.x * BM;
    const int h = blockIdx.y;
    const int b = blockIdx.z;

    const __half* Qb = Q + (size_t)(b * SEQ + q0) * DMODEL + h * DHEAD;
    const __half* Kb = K + (size_t)(b * SEQ) * DMODEL + h * DHEAD;
    const __half* Vb = V + (size_t)(b * SEQ) * DMODEL + h * DHEAD;

    const uint32_t sK = smem_u32(Ks);
    const uint32_t sV = smem_u32(Vs);

    const int ldrow = tid >> 3;       // 0..31
    const int ldoff = (tid & 7) * 8;  // halves

    auto issue_kv = [&](int t, int s) {
#pragma unroll
        for (int tt = 0; tt < 2; tt++) {
            int row = ldrow + tt * 32;
            uint32_t off = (uint32_t)(s * KVT + row * PAD + ldoff) * 2;
            const size_t gofs = (size_t)(t * BN + row) * DMODEL + ldoff;
            cp16(sK + off, Kb + gofs);
            cp16(sV + off, Vb + gofs);
        }
        cp_commit();
    };

#pragma unroll
    for (int t = 0; t < 4; t++) {
        int c = tid + t * 256;
        int row = c >> 3;
        int off = (c & 7) * 8;
        *(uint4*)&Qs[row * PAD + off] = *(const uint4*)(Qb + (size_t)row * DMODEL + off);
    }
    issue_kv(0, 0);
    issue_kv(1, 1);
    __syncthreads();

    const int rowA = (lane & 7) + 8 * ((lane >> 3) & 1);
    const int colA = 8 * (lane >> 4);
    const int rowB = (lane & 7) + 8 * (lane >> 4);
    const int colB = 8 * ((lane >> 3) & 1);

    uint32_t qf[4][4];
#pragma unroll
    for (int j = 0; j < 4; j++)
        ldmx4(qf[j][0], qf[j][1], qf[j][2], qf[j][3],
              smem_u32(&Qs[(wm + rowA) * PAD + 16 * j + colA]));

    uint32_t kAddr[4], vAddr[4];
#pragma unroll
    for (int p = 0; p < 4; p++) {
        kAddr[p] = smem_u32(&Ks[(p * 16 + rowB) * PAD + colB]);
        vAddr[p] = smem_u32(&Vs[rowA * PAD + p * 16 + colA]);
    }

    float oacc[8][4];
#pragma unroll
    for (int nt = 0; nt < 8; nt++)
#pragma unroll
        for (int e = 0; e < 4; e++) oacc[nt][e] = 0.0f;
    float m0r = -INFINITY, m1r = -INFINITY, l0r = 0.0f, l1r = 0.0f;

    const int NT = SEQ / BN;   // 32
    for (int t = 0; t < NT; t++) {
        if (t < NT - 1) cp_wait<1>(); else cp_wait<0>();
        __syncthreads();
        if (t + 2 < NT) issue_kv(t + 2, (t + 2) % 3);

        const uint32_t soff = (uint32_t)((t % 3) * KVT) * 2;

        float sacc[8][4];
#pragma unroll
        for (int nt = 0; nt < 8; nt++)
#pragma unroll
            for (int e = 0; e < 4; e++) sacc[nt][e] = 0.0f;

        // ---- S = Q K^T, software-pipelined over 16 (j,p) steps ----
        {
            uint32_t kf[2][4];
            ldmx4(kf[0][0], kf[0][1], kf[0][2], kf[0][3], kAddr[0] + soff);
#pragma unroll
            for (int kk = 0; kk < 16; kk++) {
                const int j = kk >> 2, p = kk & 3;
                if (kk < 15) {
                    const int j2 = (kk + 1) >> 2, p2 = (kk + 1) & 3;
                    ldmx4(kf[(kk + 1) & 1][0], kf[(kk + 1) & 1][1],
                          kf[(kk + 1) & 1][2], kf[(kk + 1) & 1][3],
                          kAddr[p2] + soff + 32 * j2);
                }
                const int cb = kk & 1;
                mma16816(sacc[2 * p],     qf[j][0], qf[j][1], qf[j][2], qf[j][3],
                         kf[cb][0], kf[cb][1]);
                mma16816(sacc[2 * p + 1], qf[j][0], qf[j][1], qf[j][2], qf[j][3],
                         kf[cb][2], kf[cb][3]);
            }
        }

        // softmax in exp2 domain (scores pre-scaled by log2e)
        float mx0 = -INFINITY, mx1 = -INFINITY;
#pragma unroll
        for (int nt = 0; nt < 8; nt++) {
            mx0 = fmaxf(mx0, fmaxf(sacc[nt][0], sacc[nt][1]));
            mx1 = fmaxf(mx1, fmaxf(sacc[nt][2], sacc[nt][3]));
        }
        mx0 = fmaxf(mx0, __shfl_xor_sync(0xffffffffu, mx0, 1));
        mx0 = fmaxf(mx0, __shfl_xor_sync(0xffffffffu, mx0, 2));
        mx1 = fmaxf(mx1, __shfl_xor_sync(0xffffffffu, mx1, 1));
        mx1 = fmaxf(mx1, __shfl_xor_sync(0xffffffffu, mx1, 2));

        float mn0 = fmaxf(m0r, mx0), mn1 = fmaxf(m1r, mx1);
        float a0 = exp2f(m0r - mn0), a1 = exp2f(m1r - mn1);
        m0r = mn0; m1r = mn1;

        float s0 = 0.0f, s1 = 0.0f;
        uint32_t ph[8][2];
#pragma unroll
        for (int nt = 0; nt < 8; nt++) {
            uint32_t h01 = cvt_h2(sacc[nt][0] - mn0, sacc[nt][1] - mn0);
            uint32_t h23 = cvt_h2(sacc[nt][2] - mn1, sacc[nt][3] - mn1);
            ph[nt][0] = ex2_h2(h01);
            ph[nt][1] = ex2_h2(h23);
            float2 f01 = __half22float2(*(__half2*)&ph[nt][0]);
            float2 f23 = __half22float2(*(__half2*)&ph[nt][1]);
            s0 += f01.x + f01.y;
            s1 += f23.x + f23.y;
        }
        s0 += __shfl_xor_sync(0xffffffffu, s0, 1);
        s0 += __shfl_xor_sync(0xffffffffu, s0, 2);
        s1 += __shfl_xor_sync(0xffffffffu, s1, 1);
        s1 += __shfl_xor_sync(0xffffffffu, s1, 2);
        l0r = l0r * a0 + s0;
        l1r = l1r * a1 + s1;

#pragma unroll
        for (int nt = 0; nt < 8; nt++) {
            oacc[nt][0] *= a0; oacc[nt][1] *= a0;
            oacc[nt][2] *= a1; oacc[nt][3] *= a1;
        }

        // ---- O += P V, software-pipelined over 16 (j,p) steps ----
        {
            uint32_t vf[2][4];
            ldmx4t(vf[0][0], vf[0][1], vf[0][2], vf[0][3], vAddr[0] + soff);
#pragma unroll
            for (int kk = 0; kk < 16; kk++) {
                const int j = kk >> 2, p = kk & 3;
                if (kk < 15) {
                    const int j2 = (kk + 1) >> 2, p2 = (kk + 1) & 3;
                    ldmx4t(vf[(kk + 1) & 1][0], vf[(kk + 1) & 1][1],
                           vf[(kk + 1) & 1][2], vf[(kk + 1) & 1][3],
                           vAddr[p2] + soff + 2304 * j2);
                }
                const int cb = kk & 1;
                mma16816(oacc[2 * p],     ph[2 * j][0], ph[2 * j][1],
                         ph[2 * j + 1][0], ph[2 * j + 1][1], vf[cb][0], vf[cb][1]);
                mma16816(oacc[2 * p + 1], ph[2 * j][0], ph[2 * j][1],
                         ph[2 * j + 1][0], ph[2 * j + 1][1], vf[cb][2], vf[cb][3]);
            }
        }
    }

    float inv0 = 1.0f / l0r, inv1 = 1.0f / l1r;
    __half* Ob = O + (size_t)(b * SEQ + q0 + wm) * DMODEL + h * DHEAD;
#pragma unroll
    for (int nt = 0; nt < 8; nt++) {
        int c = nt * 8 + 2 * tg;
        *(__half2*)(Ob + (size_t)g * DMODEL + c) =
            __floats2half2_rn(oacc[nt][0] * inv0, oacc[nt][1] * inv0);
        *(__half2*)(Ob + (size_t)(g + 8) * DMODEL + c) =
            __floats2half2_rn(oacc[nt][2] * inv1, oacc[nt][3] * inv1);
    }
}

// ---------------------------------------------------------------------------

extern "C" void kernel_launch(void* const* d_in, const int* in_sizes, int n_in,
                              void* d_out, int out_size)
{
    const float* X  = (const float*)d_in[0];
    const float* Wq = (const float*)d_in[1];
    const float* Wk = (const float*)d_in[2];
    const float* Wv = (const float*)d_in[3];
    const float* Wo = (const float*)d_in[4];
    float* out = (float*)d_out;

    __half *xh, *wq, *wk, *wv, *wo, *q, *k, *v, *ctx;
    cudaGetSymbolAddress((void**)&xh, g_xh);
    cudaGetSymbolAddress((void**)&wq, g_wq);
    cudaGetSymbolAddress((void**)&wk, g_wk);
    cudaGetSymbolAddress((void**)&wv, g_wv);
    cudaGetSymbolAddress((void**)&wo, g_wo);
    cudaGetSymbolAddress((void**)&q,  g_q);
    cudaGetSymbolAddress((void**)&k,  g_k);
    cudaGetSymbolAddress((void**)&v,  g_v);
    cudaGetSymbolAddress((void**)&ctx, g_ctx);

    cudaFuncSetAttribute(gemm_qkv,      cudaFuncAttributeMaxDynamicSharedMemorySize, GEMM_SMEM);
    cudaFuncSetAttribute(gemm_single_f, cudaFuncAttributeMaxDynamicSharedMemorySize, GEMM_SMEM);
    cudaFuncSetAttribute(flash_attn_h,  cudaFuncAttributeMaxDynamicSharedMemorySize, FLASH_SMEM);

    const int NX = MROWS * DMODEL;      // 8.4M
    const int NW = DMODEL * DMODEL;     // 1.05M
    cvt_f2h_all<<<dim3(2048, 5), 256>>>(X, Wq, Wk, Wv, Wo, xh, wq, wk, wv, wo, NX, NW);

    dim3 gqkv(DMODEL / 128, MROWS / 128, 3);    // (8, 64, 3)
    gemm_qkv<<<gqkv, 256, GEMM_SMEM>>>(xh, wq, wk, wv, q, k, v);

    dim3 gattn(SEQ / 128, NHEAD, BATCH);        // (16, 16, 4)
    flash_attn_h<<<gattn, 256, FLASH_SMEM>>>(q, k, v, ctx);

    dim3 gout(DMODEL / 128, MROWS / 128);       // (8, 64)
    gemm_single_f<<<gout, 256, GEMM_SMEM>>>(ctx, wo, out);
}